// round 1
// baseline (speedup 1.0000x reference)
#include <cuda_runtime.h>

// NURBS surface eval: DEG=3, N_CP=32x32, N_EVAL=2,000,000.
// Knots are clamped-uniform: [0,0,0, j/29 (j=0..29), 1,1,1]  (36 knots)
// => knot(i) = clamp(i-3, 0, 29) / 29   (no knot table needed)
// span = floor(u*29) + 3, clamped to [3,31].
//
// Output layout (tuple concat): d_out[0 .. 4N)   = points  (x/w, y/w, z/w, 1)
//                               d_out[4N .. 8N)  = normals (nx, ny, nz, 0)

#define NCP 32

__device__ __forceinline__ float knotv(int i) {
    int t = i - 3;
    t = t < 0 ? 0 : (t > 29 ? 29 : t);
    return (float)t * (1.0f / 29.0f);
}

// Cox-de Boor p=3, values N[0..3] and first derivatives D[0..3] (already *p).
__device__ __forceinline__ void basis3(float u, int span, float* Nb, float* Db) {
    float left[4], right[4];
    float ndu[4][4];
    ndu[0][0] = 1.0f;
#pragma unroll
    for (int j = 1; j <= 3; ++j) {
        left[j]  = u - knotv(span + 1 - j);
        right[j] = knotv(span + j) - u;
        float saved = 0.0f;
#pragma unroll
        for (int r = 0; r < j; ++r) {
            ndu[j][r] = right[r + 1] + left[j - r];
            float tmp = ndu[r][j - 1] / ndu[j][r];
            ndu[r][j] = saved + right[r + 1] * tmp;
            saved = left[j - r] * tmp;
        }
        ndu[j][j] = saved;
    }
    Nb[0] = ndu[0][3];
    Nb[1] = ndu[1][3];
    Nb[2] = ndu[2][3];
    Nb[3] = ndu[3][3];
    // First derivative: D[r] = p * (t[r-1] - t[r]), t[r] = ndu[r][2]/ndu[3][r]
    // (these quotients were already formed inside the j=3 iteration -> CSE)
    float t0 = ndu[0][2] / ndu[3][0];
    float t1 = ndu[1][2] / ndu[3][1];
    float t2 = ndu[2][2] / ndu[3][2];
    Db[0] = -3.0f * t0;
    Db[1] = 3.0f * (t0 - t1);
    Db[2] = 3.0f * (t1 - t2);
    Db[3] = 3.0f * t2;
}

extern "C" __global__ void __launch_bounds__(256)
nurbs_surface_kernel(const float2* __restrict__ ep,
                     const float*  __restrict__ cp,
                     float4* __restrict__ out,
                     int n)
{
    __shared__ float4 scp[NCP * NCP];   // 16 KB: control points padded to float4 (w=1)
    for (int i = threadIdx.x; i < NCP * NCP; i += blockDim.x) {
        scp[i] = make_float4(cp[3 * i + 0], cp[3 * i + 1], cp[3 * i + 2], 1.0f);
    }
    __syncthreads();

    int idx = blockIdx.x * blockDim.x + threadIdx.x;
    if (idx >= n) return;

    float2 uv = ep[idx];

    int se = (int)floorf(uv.x * 29.0f);
    se = se < 0 ? 0 : (se > 28 ? 28 : se);
    int sn = (int)floorf(uv.y * 29.0f);
    sn = sn < 0 ? 0 : (sn > 28 ? 28 : sn);

    float Nu[4], Du[4], Nv[4], Dv[4];
    basis3(uv.x, se + 3, Nu, Du);
    basis3(uv.y, sn + 3, Nv, Dv);

    // Accumulators: homogeneous point (xyzw), d/du (xyz), d/dv (xyz)
    float px = 0.f, py = 0.f, pz = 0.f, pw = 0.f;
    float ex = 0.f, ey = 0.f, ez = 0.f;
    float fx = 0.f, fy = 0.f, fz = 0.f;

    int base = se * NCP + sn;   // (span_e - p) * NCP + (span_n - q)
#pragma unroll
    for (int r = 0; r < 4; ++r) {
        const float nur = Nu[r], dur = Du[r];
#pragma unroll
        for (int s = 0; s < 4; ++s) {
            float4 g = scp[base + r * NCP + s];
            float w00 = nur * Nv[s];
            float w10 = dur * Nv[s];
            float w01 = nur * Dv[s];
            px = fmaf(w00, g.x, px);
            py = fmaf(w00, g.y, py);
            pz = fmaf(w00, g.z, pz);
            pw += w00;                 // g.w == 1
            ex = fmaf(w10, g.x, ex);
            ey = fmaf(w10, g.y, ey);
            ez = fmaf(w10, g.z, ez);
            fx = fmaf(w01, g.x, fx);
            fy = fmaf(w01, g.y, fy);
            fz = fmaf(w01, g.z, fz);
        }
    }

    float invw = 1.0f / pw;

    // normal = cross(d_e, d_n), normalized
    float cx = ey * fz - ez * fy;
    float cy = ez * fx - ex * fz;
    float cz = ex * fy - ey * fx;
    float il = rsqrtf(cx * cx + cy * cy + cz * cz);

    out[idx]     = make_float4(px * invw, py * invw, pz * invw, 1.0f);
    out[n + idx] = make_float4(cx * il, cy * il, cz * il, 0.0f);
}

extern "C" void kernel_launch(void* const* d_in, const int* in_sizes, int n_in,
                              void* d_out, int out_size)
{
    const float2* ep = (const float2*)d_in[0];   // evaluation_points (N,2)
    const float*  cp = (const float*)d_in[1];    // control_points (32,32,3)
    int n = in_sizes[0] / 2;
    float4* out = (float4*)d_out;

    int block = 256;
    int grid = (n + block - 1) / block;
    nurbs_surface_kernel<<<grid, block>>>(ep, cp, out, n);
}